// round 1
// baseline (speedup 1.0000x reference)
#include <cuda_runtime.h>
#include <math.h>

#define NN  50000
#define EE  800000
#define NNZ (EE + NN)

// ---------------- scratch (device globals; no allocation allowed) ----------
__device__ int   g_rowptr[NN + 1];
__device__ int   g_cursor[NN];
__device__ int   g_cnt[NN];
__device__ int   g_col[NNZ];
__device__ float g_val[NNZ];
__device__ float g_dinv[NN];
__device__ float g_x1[NN * 128];
__device__ float g_x2[NN * 128];
__device__ float g_h [NN * 384];
__device__ float g_g [NN * 80];    // [h@w2_0 + b2_0 | h@w2_1]
__device__ float g_g1p[NN * 40];   // P (h@w2_1)

// ---------------- graph build ---------------------------------------------
__global__ void k_init_cnt() {
    int i = blockIdx.x * blockDim.x + threadIdx.x;
    if (i < NN) g_cnt[i] = 1;                 // self loop
}

__global__ void k_count(const int* __restrict__ ei) {
    int e = blockIdx.x * blockDim.x + threadIdx.x;
    if (e < EE) atomicAdd(&g_cnt[ei[EE + e]], 1);   // dst = ei[1][e]
}

// single-block exclusive scan of g_cnt -> g_rowptr, plus dinv = rsqrt(deg)
__global__ void k_scan() {
    __shared__ int sh[1024];
    int t = threadIdx.x;
    int run = 0;
    for (int base = 0; base < NN; base += 1024) {
        int i = base + t;
        int c = (i < NN) ? g_cnt[i] : 0;
        if (i < NN) g_dinv[i] = rsqrtf((float)c);
        sh[t] = c;
        __syncthreads();
        #pragma unroll
        for (int off = 1; off < 1024; off <<= 1) {
            int y = (t >= off) ? sh[t - off] : 0;
            __syncthreads();
            sh[t] += y;
            __syncthreads();
        }
        if (i < NN) g_rowptr[i] = run + sh[t] - c;
        run += sh[1023];
        __syncthreads();
    }
    if (t == 0) g_rowptr[NN] = run;
}

__global__ void k_selfloop() {
    int i = blockIdx.x * blockDim.x + threadIdx.x;
    if (i < NN) {
        int p = g_rowptr[i];
        float d = g_dinv[i];
        g_col[p] = i;
        g_val[p] = d * d;
        g_cursor[i] = p + 1;
    }
}

__global__ void k_scatter(const int* __restrict__ ei) {
    int e = blockIdx.x * blockDim.x + threadIdx.x;
    if (e < EE) {
        int s = ei[e];
        int d = ei[EE + e];
        int p = atomicAdd(&g_cursor[d], 1);
        g_col[p] = s;
        g_val[p] = g_dinv[s] * g_dinv[d];
    }
}

// ---------------- SpMM (CSR by dst, gather, no atomics) --------------------
__device__ __forceinline__ void spmm128_body(const float* __restrict__ in,
                                             float* __restrict__ out) {
    int n = blockIdx.x;
    int t = threadIdx.x;           // 128 threads = one feature each
    int j = g_rowptr[n];
    int e = g_rowptr[n + 1];
    float a0 = 0.f, a1 = 0.f, a2 = 0.f, a3 = 0.f;
    for (; j + 4 <= e; j += 4) {
        int   c0 = g_col[j],     c1 = g_col[j + 1];
        int   c2 = g_col[j + 2], c3 = g_col[j + 3];
        float v0 = g_val[j],     v1 = g_val[j + 1];
        float v2 = g_val[j + 2], v3 = g_val[j + 3];
        a0 += v0 * in[c0 * 128 + t];
        a1 += v1 * in[c1 * 128 + t];
        a2 += v2 * in[c2 * 128 + t];
        a3 += v3 * in[c3 * 128 + t];
    }
    for (; j < e; j++) a0 += g_val[j] * in[g_col[j] * 128 + t];
    out[n * 128 + t] = (a0 + a1) + (a2 + a3);
}

__global__ void k_spmm_x1(const float* __restrict__ x) { spmm128_body(x, g_x1); }
__global__ void k_spmm_x2()                            { spmm128_body(g_x1, g_x2); }

// propagate the 40 cols of g_g[:, 40:80] -> g_g1p  (F=40, row stride 80)
__global__ void k_spmm40() {
    int n = blockIdx.x;
    int t = threadIdx.x;           // blockDim = 64, first 40 active
    if (t >= 40) return;
    int j = g_rowptr[n];
    int e = g_rowptr[n + 1];
    float a0 = 0.f, a1 = 0.f, a2 = 0.f, a3 = 0.f;
    for (; j + 4 <= e; j += 4) {
        a0 += g_val[j]     * g_g[g_col[j]     * 80 + 40 + t];
        a1 += g_val[j + 1] * g_g[g_col[j + 1] * 80 + 40 + t];
        a2 += g_val[j + 2] * g_g[g_col[j + 2] * 80 + 40 + t];
        a3 += g_val[j + 3] * g_g[g_col[j + 3] * 80 + 40 + t];
    }
    for (; j < e; j++) a0 += g_val[j] * g_g[g_col[j] * 80 + 40 + t];
    g_g1p[n * 40 + t] = (a0 + a1) + (a2 + a3);
}

// ---------------- GEMM 1: h = relu([x@w0+b0 | x1@w1+b1 | x2@w2+b2]) --------
// 64x128 tile, K=128 in 32-chunks, 256 threads, 4x8 micro-tile.
__global__ void __launch_bounds__(256) k_gemm1(
    const float* __restrict__ x,
    const float* __restrict__ w0, const float* __restrict__ b0,
    const float* __restrict__ w1, const float* __restrict__ b1,
    const float* __restrict__ w2, const float* __restrict__ b2)
{
    __shared__ __align__(16) float xT[32][68];   // k-major, padded
    __shared__ __align__(16) float ws[32][128];

    int which = blockIdx.y;
    const float* in = (which == 0) ? x  : ((which == 1) ? (const float*)g_x1 : (const float*)g_x2);
    const float* w  = (which == 0) ? w0 : ((which == 1) ? w1 : w2);
    const float* b  = (which == 0) ? b0 : ((which == 1) ? b1 : b2);

    int row0 = blockIdx.x * 64;
    int t = threadIdx.x, tx = t & 15, ty = t >> 4;

    float acc[4][8];
    #pragma unroll
    for (int i = 0; i < 4; i++)
        #pragma unroll
        for (int j = 0; j < 8; j++) acc[i][j] = 0.f;

    for (int kc = 0; kc < 128; kc += 32) {
        // weight chunk: 32x128 = 1024 float4
        #pragma unroll
        for (int i = 0; i < 4; i++) {
            int lin = t + i * 256;
            int k = lin >> 5, c4 = lin & 31;
            float4 v = *(const float4*)&w[(kc + k) * 128 + c4 * 4];
            *(float4*)&ws[k][c4 * 4] = v;
        }
        // input chunk, transposed: 64x32 = 512 float4
        #pragma unroll
        for (int i = 0; i < 2; i++) {
            int lin = t + i * 256;
            int r = lin >> 3, k4 = lin & 7;
            int row = row0 + r;
            float4 v = make_float4(0.f, 0.f, 0.f, 0.f);
            if (row < NN) v = *(const float4*)&in[row * 128 + kc + k4 * 4];
            xT[k4 * 4 + 0][r] = v.x; xT[k4 * 4 + 1][r] = v.y;
            xT[k4 * 4 + 2][r] = v.z; xT[k4 * 4 + 3][r] = v.w;
        }
        __syncthreads();
        #pragma unroll
        for (int k = 0; k < 32; k++) {
            float4 a  = *(float4*)&xT[k][ty * 4];
            float4 bA = *(float4*)&ws[k][tx * 8];
            float4 bB = *(float4*)&ws[k][tx * 8 + 4];
            float av[4] = {a.x, a.y, a.z, a.w};
            float bv[8] = {bA.x, bA.y, bA.z, bA.w, bB.x, bB.y, bB.z, bB.w};
            #pragma unroll
            for (int ii = 0; ii < 4; ii++)
                #pragma unroll
                for (int jj = 0; jj < 8; jj++)
                    acc[ii][jj] += av[ii] * bv[jj];
        }
        __syncthreads();
    }
    #pragma unroll
    for (int ii = 0; ii < 4; ii++) {
        int row = row0 + ty * 4 + ii;
        if (row < NN) {
            #pragma unroll
            for (int jj = 0; jj < 8; jj++) {
                int col = tx * 8 + jj;
                float v = acc[ii][jj] + b[col];
                g_h[row * 384 + which * 128 + col] = fmaxf(v, 0.f);
            }
        }
    }
}

// ---------------- GEMM 2: g = [h@w2_0 + b2_0 | h@w2_1] (bias_1 deferred) ---
__global__ void __launch_bounds__(256) k_gemm2(
    const float* __restrict__ w20, const float* __restrict__ b20,
    const float* __restrict__ w21)
{
    __shared__ __align__(16) float hT[32][68];
    __shared__ float ws[32][80];

    int row0 = blockIdx.x * 64;
    int t = threadIdx.x, tx = t & 15, ty = t >> 4;

    float acc[4][5];
    #pragma unroll
    for (int i = 0; i < 4; i++)
        #pragma unroll
        for (int j = 0; j < 5; j++) acc[i][j] = 0.f;

    for (int kc = 0; kc < 384; kc += 32) {
        // fused weight chunk [w2_0 | w2_1]: 32x80 floats, 10 per thread
        #pragma unroll
        for (int i = 0; i < 10; i++) {
            int lin = t + i * 256;
            int k = lin / 80, c = lin % 80;
            float v = (c < 40) ? w20[(kc + k) * 40 + c]
                               : w21[(kc + k) * 40 + (c - 40)];
            ws[k][c] = v;
        }
        // h chunk transposed
        #pragma unroll
        for (int i = 0; i < 2; i++) {
            int lin = t + i * 256;
            int r = lin >> 3, k4 = lin & 7;
            int row = row0 + r;
            float4 v = make_float4(0.f, 0.f, 0.f, 0.f);
            if (row < NN) v = *(const float4*)&g_h[row * 384 + kc + k4 * 4];
            hT[k4 * 4 + 0][r] = v.x; hT[k4 * 4 + 1][r] = v.y;
            hT[k4 * 4 + 2][r] = v.z; hT[k4 * 4 + 3][r] = v.w;
        }
        __syncthreads();
        #pragma unroll
        for (int k = 0; k < 32; k++) {
            float4 a = *(float4*)&hT[k][ty * 4];
            float av[4] = {a.x, a.y, a.z, a.w};
            float bv[5];
            #pragma unroll
            for (int j = 0; j < 5; j++) bv[j] = ws[k][tx * 5 + j];
            #pragma unroll
            for (int ii = 0; ii < 4; ii++)
                #pragma unroll
                for (int jj = 0; jj < 5; jj++)
                    acc[ii][jj] += av[ii] * bv[jj];
        }
        __syncthreads();
    }
    #pragma unroll
    for (int ii = 0; ii < 4; ii++) {
        int row = row0 + ty * 4 + ii;
        if (row < NN) {
            #pragma unroll
            for (int jj = 0; jj < 5; jj++) {
                int col = tx * 5 + jj;
                float v = acc[ii][jj] + ((col < 40) ? b20[col] : 0.f);
                g_g[row * 80 + col] = v;
            }
        }
    }
}

// ---------------- final: add b2_1 to propagated half, row log_softmax ------
__global__ void k_final(const float* __restrict__ b21, float* __restrict__ out) {
    int gt = blockIdx.x * blockDim.x + threadIdx.x;
    int n = gt >> 5, lane = gt & 31;
    if (n >= NN) return;

    float v0 = g_g[n * 80 + lane];                                   // cols 0..31 (<40)
    int   c1 = lane + 32;
    float v1 = (c1 < 40) ? g_g[n * 80 + c1]
                         : g_g1p[n * 40 + (c1 - 40)] + b21[c1 - 40]; // cols 32..63
    float v2 = -1e30f;
    if (lane < 16) {
        int c2 = lane + 64;                                          // cols 64..79
        v2 = g_g1p[n * 40 + (c2 - 40)] + b21[c2 - 40];
    }
    float m = fmaxf(fmaxf(v0, v1), v2);
    #pragma unroll
    for (int off = 16; off; off >>= 1) m = fmaxf(m, __shfl_xor_sync(0xffffffffu, m, off));
    float s = expf(v0 - m) + expf(v1 - m) + ((lane < 16) ? expf(v2 - m) : 0.f);
    #pragma unroll
    for (int off = 16; off; off >>= 1) s += __shfl_xor_sync(0xffffffffu, s, off);
    float lse = m + logf(s);

    out[n * 80 + lane] = v0 - lse;
    out[n * 80 + c1]   = v1 - lse;
    if (lane < 16) out[n * 80 + lane + 64] = v2 - lse;
}

// ---------------- launch ----------------------------------------------------
extern "C" void kernel_launch(void* const* d_in, const int* in_sizes, int n_in,
                              void* d_out, int out_size) {
    const float* x   = (const float*)d_in[0];
    const int*   ei  = (const int*)  d_in[1];
    const float* w10 = (const float*)d_in[2];
    const float* b10 = (const float*)d_in[3];
    const float* w11 = (const float*)d_in[4];
    const float* b11 = (const float*)d_in[5];
    const float* w12 = (const float*)d_in[6];
    const float* b12 = (const float*)d_in[7];
    const float* w20 = (const float*)d_in[8];
    const float* b20 = (const float*)d_in[9];
    const float* w21 = (const float*)d_in[10];
    const float* b21 = (const float*)d_in[11];
    float* out = (float*)d_out;

    // graph build (CSR by dst + symmetric norm)
    k_init_cnt<<<(NN + 255) / 256, 256>>>();
    k_count   <<<(EE + 255) / 256, 256>>>(ei);
    k_scan    <<<1, 1024>>>();
    k_selfloop<<<(NN + 255) / 256, 256>>>();
    k_scatter <<<(EE + 255) / 256, 256>>>(ei);

    // conv1 propagations
    k_spmm_x1<<<NN, 128>>>(x);
    k_spmm_x2<<<NN, 128>>>();

    // conv1 fused GEMM + bias + relu
    dim3 grid1((NN + 63) / 64, 3);
    k_gemm1<<<grid1, 256>>>(x, w10, b10, w11, b11, w12, b12);

    // conv2 GEMM (both halves), then propagate only the 40-wide half
    k_gemm2<<<(NN + 63) / 64, 256>>>(w20, b20, w21);
    k_spmm40<<<NN, 64>>>();

    // bias + log_softmax
    k_final<<<(NN * 32 + 255) / 256, 256>>>(b21, out);
}